// round 5
// baseline (speedup 1.0000x reference)
#include <cuda_runtime.h>
#include <math.h>

#define B  32
#define L  2048
#define H  1024
#define K2 2048   // 2*H

#define GS 64     // g-splits for u partials
#define HS 64     // h-splits for v partials

// Scratch (no allocations allowed anywhere)
__device__ float g_part_u[GS * B * H];    // 8 MB  (L2-hot)
__device__ float g_u[B * H];              // 128 KB
__device__ float g_part_v[HS * B * K2];   // 16 MB (L2-hot)
__device__ float g_v[B * K2];             // 256 KB
__device__ float g_scores[B * L];         // 256 KB

// --------------------------- software grid barrier -------------------------
// Sense-reversing: count resets to 0 after each barrier, phase is monotonic
// (replay-safe: state is identical at every kernel entry except the phase
// value, which is only ever compared for equality).
__device__ unsigned g_bar_cnt   = 0;
__device__ unsigned g_bar_phase = 0;

__device__ __forceinline__ void grid_barrier() {
    __threadfence();                       // release my writes (all threads)
    __syncthreads();
    if (threadIdx.x == 0) {
        unsigned ph = atomicAdd(&g_bar_phase, 0u);
        if (atomicAdd(&g_bar_cnt, 1u) == gridDim.x - 1u) {
            g_bar_cnt = 0;
            __threadfence();
            atomicAdd(&g_bar_phase, 1u);
        } else {
            while (atomicAdd(&g_bar_phase, 0u) == ph) __nanosleep(128);
        }
    }
    __syncthreads();
    __threadfence();                       // acquire
}

// ---------------------------------------------------------------------------
// Kernel 1 (persistent, grid 592 = 148*4): the whole prologue in one launch.
//   Phase A : u_part[s,b,h] = sum_{g in 16-chunk s} hid[b,g]*aW[g,h]
//   Phase A2: u = sum_s u_part
//   Phase B : v_part[s,b,k] = sum_{h in 16-chunk s} u[b,h]*rW[h,k]
//   Phase C : v = sum_s v_part
// Weights aW (4MB) and rW (8MB) each read exactly once from DRAM.
// ---------------------------------------------------------------------------
__global__ void __launch_bounds__(256, 4) k_prologue(
        const float* __restrict__ hid,
        const float* __restrict__ aW,
        const float* __restrict__ rW) {
    __shared__ float4 s_stage[2][B][4];    // 4 KB, reused by phases A and B
    const int sub  = threadIdx.x >> 7;     // two 128-thread sub-blocks
    const int t128 = threadIdx.x & 127;
    const int bb   = t128 >> 2, cc = t128 & 3;

    // ---- Phase A: u partials. 512 vblocks = (8 h-tiles) x (64 g-splits) ----
    for (int vb = blockIdx.x * 2 + sub; vb < 8 * GS; vb += gridDim.x * 2) {
        const int gx = vb & 7, gy = vb >> 3;
        const int h  = (gx << 7) + t128;
        const int g0 = gy << 4;

        s_stage[sub][bb][cc] = ((const float4*)hid)[bb * (H / 4) + (g0 >> 2) + cc];
        __syncthreads();

        float acc[B];
#pragma unroll
        for (int b = 0; b < B; b++) acc[b] = 0.f;
#pragma unroll
        for (int c = 0; c < 4; c++) {
            const float* ap = aW + (size_t)(g0 + 4 * c) * H + h;
            float a0 = ap[0], a1 = ap[H], a2 = ap[2 * H], a3 = ap[3 * H];
#pragma unroll
            for (int b = 0; b < B; b++) {
                float4 h4 = s_stage[sub][b][c];
                acc[b] = fmaf(a0, h4.x, fmaf(a1, h4.y,
                          fmaf(a2, h4.z, fmaf(a3, h4.w, acc[b]))));
            }
        }
        float* outp = g_part_u + (size_t)gy * (B * H) + h;
#pragma unroll
        for (int b = 0; b < B; b++) outp[b * H] = acc[b];
        __syncthreads();
    }
    grid_barrier();

    // ---- Phase A2: u reduce (8192 float4 outputs, L2-hot partials) ----
    for (int i = blockIdx.x * 256 + threadIdx.x; i < B * H / 4;
         i += gridDim.x * 256) {
        const float4* p = (const float4*)g_part_u + i;
        float4 s = make_float4(0.f, 0.f, 0.f, 0.f);
#pragma unroll
        for (int q = 0; q < GS; q++) {
            float4 t = __ldcg(p + (size_t)q * (B * H / 4));
            s.x += t.x; s.y += t.y; s.z += t.z; s.w += t.w;
        }
        ((float4*)g_u)[i] = s;
    }
    grid_barrier();

    // ---- Phase B: v partials. 1024 vblocks = (16 k-tiles) x (64 h-splits) ----
    for (int vb = blockIdx.x * 2 + sub; vb < 16 * HS; vb += gridDim.x * 2) {
        const int kx = vb & 15, hy = vb >> 4;
        const int k  = (kx << 7) + t128;
        const int h0 = hy << 4;

        s_stage[sub][bb][cc] = __ldcg((const float4*)g_u + bb * (H / 4) + (h0 >> 2) + cc);
        __syncthreads();

        float acc[B];
#pragma unroll
        for (int b = 0; b < B; b++) acc[b] = 0.f;
#pragma unroll
        for (int c = 0; c < 4; c++) {
            const float* rp = rW + (size_t)(h0 + 4 * c) * K2 + k;
            float r0 = rp[0], r1 = rp[K2], r2 = rp[2 * K2], r3 = rp[3 * K2];
#pragma unroll
            for (int b = 0; b < B; b++) {
                float4 u4 = s_stage[sub][b][c];
                acc[b] = fmaf(r0, u4.x, fmaf(r1, u4.y,
                          fmaf(r2, u4.z, fmaf(r3, u4.w, acc[b]))));
            }
        }
        float* outp = g_part_v + (size_t)hy * (B * K2) + k;
#pragma unroll
        for (int b = 0; b < B; b++) outp[b * K2] = acc[b];
        __syncthreads();
    }
    grid_barrier();

    // ---- Phase C: v reduce (16384 float4 outputs) ----
    for (int i = blockIdx.x * 256 + threadIdx.x; i < B * K2 / 4;
         i += gridDim.x * 256) {
        const float4* p = (const float4*)g_part_v + i;
        float4 s = make_float4(0.f, 0.f, 0.f, 0.f);
#pragma unroll
        for (int q = 0; q < HS; q++) {
            float4 t = __ldcg(p + (size_t)q * (B * K2 / 4));
            s.x += t.x; s.y += t.y; s.z += t.z; s.w += t.w;
        }
        ((float4*)g_v)[i] = s;
    }
}

// ---------------------------------------------------------------------------
// Kernel 2 (persistent, grid 1184 = 148*8, regs forced <=32 like R4's 84.5%-
// DRAM version): scores phase over 8192 tiles, grid barrier, softmax phase.
//   scores[b,l] = v[b] . enc[l,b,:]   (one 8KB row per warp, 16 LDG.128 batch)
// ---------------------------------------------------------------------------
__global__ void __launch_bounds__(256, 8) k_scores_softmax(
        const float* __restrict__ enc, float* __restrict__ out) {
    __shared__ float4 sv[K2 / 4];                 // 8 KB
    const int w    = threadIdx.x >> 5;
    const int lane = threadIdx.x & 31;

    // ---- scores phase: tiles t = (x, b), 8 rows per tile (one per warp) ----
    for (int t = blockIdx.x; t < (L / 8) * B; t += gridDim.x) {
        const int b = t & 31, x = t >> 5;

        const float4* v4 = (const float4*)g_v + b * (K2 / 4);
        for (int i = threadIdx.x; i < K2 / 4; i += 256) sv[i] = __ldcg(v4 + i);
        __syncthreads();

        const int l = x * 8 + w;
        const float4* e4 = (const float4*)(enc + ((size_t)l * B + b) * K2);

        float4 e[16];
#pragma unroll
        for (int j = 0; j < 16; j++) e[j] = __ldcs(&e4[lane + 32 * j]);

        float ax = 0.f, ay = 0.f, az = 0.f, aw = 0.f;
#pragma unroll
        for (int j = 0; j < 16; j++) {
            float4 vv = sv[lane + 32 * j];
            ax += e[j].x * vv.x; ay += e[j].y * vv.y;
            az += e[j].z * vv.z; aw += e[j].w * vv.w;
        }
        float acc = (ax + ay) + (az + aw);
#pragma unroll
        for (int o = 16; o; o >>= 1)
            acc += __shfl_xor_sync(0xffffffffu, acc, o);
        if (lane == 0) g_scores[b * L + l] = acc;
        __syncthreads();                          // WAR on sv before restage
    }

    grid_barrier();

    // ---- softmax phase: 32 blocks, one batch row each ----
    if (blockIdx.x < B) {
        const int b   = blockIdx.x;
        const int tid = threadIdx.x;
        __shared__ float s_red[8];

        float vals[8];
        float m = -INFINITY;
#pragma unroll
        for (int i = 0; i < 8; i++) {
            vals[i] = __ldcg(&g_scores[b * L + tid + i * 256]);
            m = fmaxf(m, vals[i]);
        }
#pragma unroll
        for (int o = 16; o; o >>= 1)
            m = fmaxf(m, __shfl_xor_sync(0xffffffffu, m, o));
        if (lane == 0) s_red[w] = m;
        __syncthreads();
        float bm = s_red[0];
#pragma unroll
        for (int i = 1; i < 8; i++) bm = fmaxf(bm, s_red[i]);
        __syncthreads();

        float s = 0.f;
#pragma unroll
        for (int i = 0; i < 8; i++) { vals[i] = expf(vals[i] - bm); s += vals[i]; }
#pragma unroll
        for (int o = 16; o; o >>= 1) s += __shfl_xor_sync(0xffffffffu, s, o);
        if (lane == 0) s_red[w] = s;
        __syncthreads();
        float bs = 0.f;
#pragma unroll
        for (int i = 0; i < 8; i++) bs += s_red[i];

        const float inv = 1.f / bs;
#pragma unroll
        for (int i = 0; i < 8; i++)
            out[b * L + tid + i * 256] = vals[i] * inv;
    }
}

// ---------------------------------------------------------------------------
extern "C" void kernel_launch(void* const* d_in, const int* in_sizes, int n_in,
                              void* d_out, int out_size) {
    const float* hid = (const float*)d_in[0];  // [B, H]
    const float* enc = (const float*)d_in[1];  // [L, B, 2H]
    const float* rW  = (const float*)d_in[2];  // [H, 2H]
    // d_in[3] = reduce_b, d_in[5] = attn_b: constant per batch over l ->
    // invariant under softmax, provably unused.
    const float* aW  = (const float*)d_in[4];  // [H, H]
    float* out = (float*)d_out;                // [B, L]

    k_prologue<<<148 * 4, 256>>>(hid, aW, rW);
    k_scores_softmax<<<148 * 8, 256>>>(enc, out);
}

// round 6
// speedup vs baseline: 1.0870x; 1.0870x over previous
#include <cuda_runtime.h>
#include <math.h>

#define B  32
#define L  2048
#define H  1024
#define K2 2048   // 2*H

#define GS 32     // g-splits for u partials
#define HS 32     // h-splits for v partials

// Scratch (no allocations allowed anywhere)
__device__ float g_part_u[GS * B * H];    // 4 MB  (L2-hot)
__device__ float g_u[B * H];              // 128 KB
__device__ float g_part_v[HS * B * K2];   // 8 MB  (L2-hot)
__device__ float g_v[B * K2];             // 256 KB
__device__ float g_scores[B * L];         // 256 KB

// ---------------------------------------------------------------------------
// Kernel 1: partial u[b,h] = sum_{g in 32-chunk} hid[b,g] * attn_W[g,h]
// grid (8, 32) = 256 blocks, block 128. aW (4 MB) read exactly once.
// 32 independent strided LDGs per thread (fully unrolled) for max MLP.
// ---------------------------------------------------------------------------
__global__ void k_u_partial(const float* __restrict__ hid,
                            const float* __restrict__ aW) {
    const int h  = blockIdx.x * 128 + threadIdx.x;
    const int g0 = blockIdx.y * 32;
    __shared__ float4 s_hid[B][8];                  // 32 x 32 floats = 4 KB
    for (int i = threadIdx.x; i < B * 8; i += 128) {
        int b = i >> 3, c = i & 7;
        s_hid[b][c] = ((const float4*)(hid + b * H + g0))[c];
    }
    __syncthreads();

    float acc[B];
#pragma unroll
    for (int b = 0; b < B; b++) acc[b] = 0.f;

#pragma unroll
    for (int c = 0; c < 8; c++) {
        const float* ap = aW + (size_t)(g0 + 4 * c) * H + h;
        float a0 = ap[0], a1 = ap[H], a2 = ap[2 * H], a3 = ap[3 * H];
#pragma unroll
        for (int b = 0; b < B; b++) {
            float4 h4 = s_hid[b][c];
            acc[b] = fmaf(a0, h4.x, fmaf(a1, h4.y,
                      fmaf(a2, h4.z, fmaf(a3, h4.w, acc[b]))));
        }
    }
    float* outp = g_part_u + (size_t)blockIdx.y * (B * H) + h;
#pragma unroll
    for (int b = 0; b < B; b++) outp[b * H] = acc[b];
}

// Kernel 2: u = sum over GS partials (L2-hot, 4 MB read / 128 KB write)
__global__ void k_u_reduce() {
    int i = blockIdx.x * 128 + threadIdx.x;         // over B*H/4 = 8192
    const float4* p = (const float4*)g_part_u + i;
    float4 s = make_float4(0.f, 0.f, 0.f, 0.f);
#pragma unroll
    for (int q = 0; q < GS; q++) {
        float4 t = p[(size_t)q * (B * H / 4)];
        s.x += t.x; s.y += t.y; s.z += t.z; s.w += t.w;
    }
    ((float4*)g_u)[i] = s;
}

// ---------------------------------------------------------------------------
// Kernel 3: partial v[b,k] = sum_{h in 32-chunk} u[b,h] * reduce_W[h,k]
// grid (16, 32) = 512 blocks, block 128. rW (8 MB) read exactly once.
// Stages g_u directly (4 KB per block -> 2 MB total, NOT the 64 MB the old
// fused staging caused).
// ---------------------------------------------------------------------------
__global__ void k_v_partial(const float* __restrict__ rW) {
    const int k  = blockIdx.x * 128 + threadIdx.x;
    const int h0 = blockIdx.y * 32;
    __shared__ float4 s_u[B][8];                    // 4 KB
    for (int i = threadIdx.x; i < B * 8; i += 128) {
        int b = i >> 3, c = i & 7;
        s_u[b][c] = ((const float4*)(g_u + b * H + h0))[c];
    }
    __syncthreads();

    float acc[B];
#pragma unroll
    for (int b = 0; b < B; b++) acc[b] = 0.f;

#pragma unroll
    for (int c = 0; c < 8; c++) {
        const float* rp = rW + (size_t)(h0 + 4 * c) * K2 + k;
        float r0 = rp[0], r1 = rp[K2], r2 = rp[2 * K2], r3 = rp[3 * K2];
#pragma unroll
        for (int b = 0; b < B; b++) {
            float4 u4 = s_u[b][c];
            acc[b] = fmaf(r0, u4.x, fmaf(r1, u4.y,
                      fmaf(r2, u4.z, fmaf(r3, u4.w, acc[b]))));
        }
    }
    float* outp = g_part_v + (size_t)blockIdx.y * (B * K2) + k;
#pragma unroll
    for (int b = 0; b < B; b++) outp[b * K2] = acc[b];
}

// Kernel 4: v = sum over HS partials (L2-hot, 8 MB read / 256 KB write)
__global__ void k_v_reduce() {
    int i = blockIdx.x * 128 + threadIdx.x;         // over B*K2/4 = 16384
    const float4* p = (const float4*)g_part_v + i;
    float4 s = make_float4(0.f, 0.f, 0.f, 0.f);
#pragma unroll
    for (int q = 0; q < HS; q++) {
        float4 t = p[(size_t)q * (B * K2 / 4)];
        s.x += t.x; s.y += t.y; s.z += t.z; s.w += t.w;
    }
    ((float4*)g_v)[i] = s;
}

// ---------------------------------------------------------------------------
// Kernel 5 (HBM-bound, IDENTICAL to R4's 84.5%-DRAM version):
// scores[b,l] = v[b] . enc[l,b,:]. One row per warp, grid (L/8, B),
// block 256, launch_bounds(256,8) -> 32 regs, ~full occupancy.
// ---------------------------------------------------------------------------
__global__ void __launch_bounds__(256, 8) k_scores(const float* __restrict__ enc) {
    const int b    = blockIdx.y;
    const int w    = threadIdx.x >> 5;
    const int lane = threadIdx.x & 31;

    __shared__ float4 sv[K2 / 4];                   // 8 KB
    const float4* v4 = (const float4*)(g_v + b * K2);
    for (int i = threadIdx.x; i < K2 / 4; i += 256) sv[i] = v4[i];
    __syncthreads();

    const int l = blockIdx.x * 8 + w;
    const float4* e4 = (const float4*)(enc + ((size_t)l * B + b) * K2);

    float4 e[16];
#pragma unroll
    for (int j = 0; j < 16; j++) e[j] = __ldcs(&e4[lane + 32 * j]);

    float ax = 0.f, ay = 0.f, az = 0.f, aw = 0.f;
#pragma unroll
    for (int j = 0; j < 16; j++) {
        float4 vv = sv[lane + 32 * j];
        ax += e[j].x * vv.x; ay += e[j].y * vv.y;
        az += e[j].z * vv.z; aw += e[j].w * vv.w;
    }
    float acc = (ax + ay) + (az + aw);
#pragma unroll
    for (int o = 16; o; o >>= 1)
        acc += __shfl_xor_sync(0xffffffffu, acc, o);
    if (lane == 0) g_scores[b * L + l] = acc;
}

// ---------------------------------------------------------------------------
// Kernel 6: row softmax over L=2048 per batch. grid B, block 256.
// ---------------------------------------------------------------------------
__global__ void k_softmax(float* __restrict__ out) {
    const int b    = blockIdx.x;
    const int tid  = threadIdx.x;
    const int w    = tid >> 5, lane = tid & 31;
    __shared__ float s_red[8];

    float vals[8];
    float m = -INFINITY;
#pragma unroll
    for (int i = 0; i < 8; i++) {
        vals[i] = g_scores[b * L + tid + i * 256];
        m = fmaxf(m, vals[i]);
    }
#pragma unroll
    for (int o = 16; o; o >>= 1) m = fmaxf(m, __shfl_xor_sync(0xffffffffu, m, o));
    if (lane == 0) s_red[w] = m;
    __syncthreads();
    float bm = s_red[0];
#pragma unroll
    for (int i = 1; i < 8; i++) bm = fmaxf(bm, s_red[i]);
    __syncthreads();

    float s = 0.f;
#pragma unroll
    for (int i = 0; i < 8; i++) { vals[i] = expf(vals[i] - bm); s += vals[i]; }
#pragma unroll
    for (int o = 16; o; o >>= 1) s += __shfl_xor_sync(0xffffffffu, s, o);
    if (lane == 0) s_red[w] = s;
    __syncthreads();
    float bs = 0.f;
#pragma unroll
    for (int i = 0; i < 8; i++) bs += s_red[i];

    const float inv = 1.f / bs;
#pragma unroll
    for (int i = 0; i < 8; i++) out[b * L + tid + i * 256] = vals[i] * inv;
}

// ---------------------------------------------------------------------------
extern "C" void kernel_launch(void* const* d_in, const int* in_sizes, int n_in,
                              void* d_out, int out_size) {
    const float* hid = (const float*)d_in[0];  // [B, H]
    const float* enc = (const float*)d_in[1];  // [L, B, 2H]
    const float* rW  = (const float*)d_in[2];  // [H, 2H]
    // d_in[3] = reduce_b, d_in[5] = attn_b: constant per batch over l ->
    // invariant under softmax, provably unused.
    const float* aW  = (const float*)d_in[4];  // [H, H]
    float* out = (float*)d_out;                // [B, L]

    k_u_partial<<<dim3(8, GS), 128>>>(hid, aW);
    k_u_reduce<<<64, 128>>>();
    k_v_partial<<<dim3(16, HS), 128>>>(rW);
    k_v_reduce<<<128, 128>>>();
    k_scores<<<dim3(L / 8, B), 256>>>(enc);
    k_softmax<<<B, 256>>>(out);
}